// round 13
// baseline (speedup 1.0000x reference)
#include <cuda_runtime.h>
#include <cuda_bf16.h>
#include <mma.h>
#include <math.h>

using namespace nvcuda;

#define N_NODES 50000
#define N_EDGES 800000
#define E_TOT   850000          // + self loops
#define C       64
#define NC      (N_NODES * C)   // 3,200,000
#define NH      (N_NODES * 4)   // 200,000

// ---- scratch layout (floats; ints/bf16 aliased) ----
// AGG region holds bf16 hi [N*256] then bf16 lo [N*256] (= N*256 floats total)
#define OFF_AGG   0
#define SZ_AGG    (N_NODES * 256)          // 12,800,000 floats
#define OFF_ALS   (OFF_AGG + SZ_AGG)
#define OFF_ALD   (OFF_ALS + NH)
#define OFF_H1    (OFF_ALD + NH)
#define OFF_STATS (OFF_H1 + NC)            // 256 (two layers x 128)
#define OFF_WA    (OFF_STATS + 256)        // 1024 (two layers x 512)
#define OFF_WHL   (OFF_WA + 1024)          // bf16[2][2][16384] = 32768 floats
#define SZ_WHL    32768
#define OFF_DEG   (OFF_WHL + SZ_WHL)       // ints
#define OFF_ROWP  (OFF_DEG + N_NODES)
#define OFF_CUR   (OFF_ROWP + N_NODES)
#define OFF_CSRC  (OFF_CUR + N_NODES)
#define SCRATCH_TOTAL (OFF_CSRC + E_TOT)

__device__ __align__(16) float g_scratch[SCRATCH_TOTAL];
__device__ int g_is64;

__device__ __forceinline__ float lrelu(float x) { return x > 0.f ? x : 0.2f * x; }

__device__ __forceinline__ void edge_endpoints(const void* ei, int e, int& s, int& d) {
    if (e < N_EDGES) {
        if (g_is64) {
            const long long* p = (const long long*)ei;
            s = (int)p[e]; d = (int)p[N_EDGES + e];
        } else {
            const int* p = (const int*)ei;
            s = p[e]; d = p[N_EDGES + e];
        }
    } else {
        s = d = e - N_EDGES;
    }
}

// ---------------------------------------------------------------------------
// init: zero degree counters + detect edge dtype
// ---------------------------------------------------------------------------
__global__ void init_kernel(const int* __restrict__ ei32, int* __restrict__ deg) {
    int i = blockIdx.x * blockDim.x + threadIdx.x;
    if (i == 0) {
        int all0 = 1;
        #pragma unroll 8
        for (int k = 0; k < 64; k++) all0 &= (ei32[2 * k + 1] == 0);
        g_is64 = all0;
    }
    if (i < N_NODES) deg[i] = 0;
}

// ---------------------------------------------------------------------------
// hist: 2 edges per thread, vectorized dst loads
// ---------------------------------------------------------------------------
__global__ void hist_kernel(const void* __restrict__ ei, int* __restrict__ deg) {
    int t = blockIdx.x * blockDim.x + threadIdx.x;
    int e0 = t * 2;
    if (e0 >= E_TOT) return;
    if (e0 + 1 < N_EDGES) {
        int d0, d1;
        if (g_is64) {
            longlong2 dd = ((const longlong2*)((const long long*)ei + N_EDGES))[t];
            d0 = (int)dd.x; d1 = (int)dd.y;
        } else {
            int2 dd = ((const int2*)((const int*)ei + N_EDGES))[t];
            d0 = dd.x; d1 = dd.y;
        }
        atomicAdd(&deg[d0], 1);
        atomicAdd(&deg[d1], 1);
    } else {
        for (int e = e0; e < e0 + 2 && e < E_TOT; e++) {
            int s, d; edge_endpoints(ei, e, s, d); (void)s;
            atomicAdd(&deg[d], 1);
        }
    }
}

#define SCAN_T 1024
#define SCAN_CHUNK 49
__global__ __launch_bounds__(SCAN_T) void scan_kernel(const int* __restrict__ deg,
                                                      int* __restrict__ row_ptr,
                                                      int* __restrict__ cursor) {
    __shared__ int sm[SCAN_T];
    int t = threadIdx.x;
    int base = t * SCAN_CHUNK;
    int s = 0;
    for (int i = 0; i < SCAN_CHUNK; i++) {
        int idx = base + i;
        if (idx < N_NODES) s += deg[idx];
    }
    sm[t] = s;
    __syncthreads();
    for (int off = 1; off < SCAN_T; off <<= 1) {
        int v = 0;
        if (t >= off) v = sm[t - off];
        __syncthreads();
        if (t >= off) sm[t] += v;
        __syncthreads();
    }
    int ex = (t == 0) ? 0 : sm[t - 1];
    for (int i = 0; i < SCAN_CHUNK; i++) {
        int idx = base + i;
        if (idx < N_NODES) {
            row_ptr[idx] = ex;
            cursor[idx] = ex;
            ex += deg[idx];
        }
    }
}

// ---------------------------------------------------------------------------
// scatter: 2 edges per thread, vectorized loads
// ---------------------------------------------------------------------------
__global__ void scatter_kernel(const void* __restrict__ ei, int* __restrict__ cursor,
                               int* __restrict__ csr_src) {
    int t = blockIdx.x * blockDim.x + threadIdx.x;
    int e0 = t * 2;
    if (e0 >= E_TOT) return;
    if (e0 + 1 < N_EDGES) {
        int s0, s1, d0, d1;
        if (g_is64) {
            longlong2 ss = ((const longlong2*)((const long long*)ei))[t];
            longlong2 dd = ((const longlong2*)((const long long*)ei + N_EDGES))[t];
            s0 = (int)ss.x; s1 = (int)ss.y; d0 = (int)dd.x; d1 = (int)dd.y;
        } else {
            int2 ss = ((const int2*)((const int*)ei))[t];
            int2 dd = ((const int2*)((const int*)ei + N_EDGES))[t];
            s0 = ss.x; s1 = ss.y; d0 = dd.x; d1 = dd.y;
        }
        int p0 = atomicAdd(&cursor[d0], 1);
        int p1 = atomicAdd(&cursor[d1], 1);
        csr_src[p0] = s0;
        csr_src[p1] = s1;
    } else {
        for (int e = e0; e < e0 + 2 && e < E_TOT; e++) {
            int s, d; edge_endpoints(ei, e, s, d);
            int pos = atomicAdd(&cursor[d], 1);
            csr_src[pos] = s;
        }
    }
}

// ---------------------------------------------------------------------------
// wa precompute for BOTH layers (block per layer) + zero stats
// ---------------------------------------------------------------------------
__global__ void wa_kernel(const float* __restrict__ W0, const float* __restrict__ as0,
                          const float* __restrict__ ad0,
                          const float* __restrict__ W1, const float* __restrict__ as1,
                          const float* __restrict__ ad1,
                          float* __restrict__ wa, float* __restrict__ stats) {
    int l = blockIdx.x;
    const float* W    = l ? W1 : W0;
    const float* asrc = l ? as1 : as0;
    const float* adst = l ? ad1 : ad0;
    int t = threadIdx.x;            // 256 threads
    int h = t >> 6, ci = t & 63;
    float s = 0.f, d = 0.f;
    #pragma unroll 8
    for (int c = 0; c < 64; c++) {
        float w = W[ci * 256 + h * 64 + c];
        s += w * asrc[h * 64 + c];
        d += w * adst[h * 64 + c];
    }
    wa[l * 512 + h * 64 + ci] = s;
    wa[l * 512 + 256 + h * 64 + ci] = d;
    if (t < 128) stats[l * 128 + t] = 0.f;
}

// ---------------------------------------------------------------------------
// Wcat split-bf16 precompute (both layers): whl[l] = {hi[256*64], lo[256*64]}
// Wcat[k=h*64+c][j] = W[c*256 + h*64 + j]
// ---------------------------------------------------------------------------
__global__ void wcat_kernel(const float* __restrict__ W0, const float* __restrict__ W1,
                            __nv_bfloat16* __restrict__ whl) {
    int l = blockIdx.y;
    const float* W = l ? W1 : W0;
    int idx = blockIdx.x * blockDim.x + threadIdx.x;   // [0, 16384)
    if (idx >= 16384) return;
    int k = idx >> 6, j = idx & 63;
    int h = k >> 6, c = k & 63;
    float w = W[c * 256 + h * 64 + j];
    __nv_bfloat16 hi = __float2bfloat16(w);
    __nv_bfloat16 lo = __float2bfloat16(w - __bfloat162float(hi));
    whl[l * 32768 + idx] = hi;
    whl[l * 32768 + 16384 + idx] = lo;
}

// ---------------------------------------------------------------------------
// attention logits, warp per node
// ---------------------------------------------------------------------------
__global__ __launch_bounds__(256) void al_kernel(const float* __restrict__ x,
                                                 const float* __restrict__ wa,
                                                 float* __restrict__ als,
                                                 float* __restrict__ ald) {
    __shared__ float swa[512];
    for (int i = threadIdx.x; i < 512; i += 256) swa[i] = wa[i];
    __syncthreads();
    int w = (blockIdx.x * blockDim.x + threadIdx.x) >> 5;
    int lane = threadIdx.x & 31;
    if (w >= N_NODES) return;
    float2 v = ((const float2*)x)[(size_t)w * 32 + lane];
    float rs[4], rd[4];
    #pragma unroll
    for (int h = 0; h < 4; h++) {
        rs[h] = v.x * swa[h * 64 + 2 * lane] + v.y * swa[h * 64 + 2 * lane + 1];
        rd[h] = v.x * swa[256 + h * 64 + 2 * lane] + v.y * swa[256 + h * 64 + 2 * lane + 1];
    }
    #pragma unroll
    for (int o = 16; o; o >>= 1) {
        #pragma unroll
        for (int h = 0; h < 4; h++) {
            rs[h] += __shfl_xor_sync(0xffffffffu, rs[h], o);
            rd[h] += __shfl_xor_sync(0xffffffffu, rd[h], o);
        }
    }
    if (lane == 0) {
        *(float4*)(als + (size_t)w * 4) = make_float4(rs[0], rs[1], rs[2], rs[3]);
        *(float4*)(ald + (size_t)w * 4) = make_float4(rd[0], rd[1], rd[2], rd[3]);
    }
}

// ---------------------------------------------------------------------------
// SINGLE-PASS fused softmax + gather. Warp per dst node.
// Epilogue writes agg as split bf16 (hi, lo) for the tensor-core GEMM.
// ---------------------------------------------------------------------------
__global__ __launch_bounds__(256) void dst_kernel(const int* __restrict__ row_ptr,
                                                  const int* __restrict__ deg,
                                                  const int* __restrict__ csr_src,
                                                  const float* __restrict__ als,
                                                  const float* __restrict__ ald,
                                                  const float* __restrict__ x,
                                                  __nv_bfloat162* __restrict__ aggh,
                                                  __nv_bfloat162* __restrict__ aggl) {
    int w = (blockIdx.x * blockDim.x + threadIdx.x) >> 5;
    int lane = threadIdx.x & 31;
    if (w >= N_NODES) return;
    int start = row_ptr[w];
    int n = deg[w];
    float4 ad = *(const float4*)(ald + (size_t)w * 4);

    float4 dl = make_float4(0.f, 0.f, 0.f, 0.f);
    float2 r0 = make_float2(0.f, 0.f), r1 = r0, r2 = r0, r3 = r0;

    for (int base = 0; base < n; base += 32) {
        int j = base + lane;
        int s = 0;
        float4 p = make_float4(0.f, 0.f, 0.f, 0.f);
        if (j < n) {
            s = csr_src[start + j];
            float4 a = *(const float4*)(als + (size_t)s * 4);
            p.x = __expf(lrelu(a.x + ad.x));
            p.y = __expf(lrelu(a.y + ad.y));
            p.z = __expf(lrelu(a.z + ad.z));
            p.w = __expf(lrelu(a.w + ad.w));
        }
        dl.x += p.x; dl.y += p.y; dl.z += p.z; dl.w += p.w;
        int cnt = n - base; if (cnt > 32) cnt = 32;
        #pragma unroll 4
        for (int jj = 0; jj < cnt; jj++) {
            int ss   = __shfl_sync(0xffffffffu, s, jj);
            float a0 = __shfl_sync(0xffffffffu, p.x, jj);
            float a1 = __shfl_sync(0xffffffffu, p.y, jj);
            float a2 = __shfl_sync(0xffffffffu, p.z, jj);
            float a3 = __shfl_sync(0xffffffffu, p.w, jj);
            float2 v = *((const float2*)x + (size_t)ss * 32 + lane);
            r0.x += a0 * v.x; r0.y += a0 * v.y;
            r1.x += a1 * v.x; r1.y += a1 * v.y;
            r2.x += a2 * v.x; r2.y += a2 * v.y;
            r3.x += a3 * v.x; r3.y += a3 * v.y;
        }
    }
    #pragma unroll
    for (int o = 16; o; o >>= 1) {
        dl.x += __shfl_xor_sync(0xffffffffu, dl.x, o);
        dl.y += __shfl_xor_sync(0xffffffffu, dl.y, o);
        dl.z += __shfl_xor_sync(0xffffffffu, dl.z, o);
        dl.w += __shfl_xor_sync(0xffffffffu, dl.w, o);
    }
    float i0 = 1.0f / (dl.x + 1e-16f);
    float i1 = 1.0f / (dl.y + 1e-16f);
    float i2 = 1.0f / (dl.z + 1e-16f);
    float i3 = 1.0f / (dl.w + 1e-16f);
    float2 o0 = make_float2(r0.x * i0, r0.y * i0);
    float2 o1 = make_float2(r1.x * i1, r1.y * i1);
    float2 o2 = make_float2(r2.x * i2, r2.y * i2);
    float2 o3 = make_float2(r3.x * i3, r3.y * i3);

    size_t base4 = (size_t)w * 128 + lane;   // bf16x2 units; head stride 32
    #define SPLIT_STORE(off, v)                                            \
        {                                                                  \
            __nv_bfloat16 hx = __float2bfloat16((v).x);                    \
            __nv_bfloat16 hy = __float2bfloat16((v).y);                    \
            __nv_bfloat162 hi2; hi2.x = hx; hi2.y = hy;                    \
            __nv_bfloat162 lo2;                                            \
            lo2.x = __float2bfloat16((v).x - __bfloat162float(hx));        \
            lo2.y = __float2bfloat16((v).y - __bfloat162float(hy));        \
            aggh[base4 + (off)] = hi2;                                     \
            aggl[base4 + (off)] = lo2;                                     \
        }
    SPLIT_STORE(0, o0)
    SPLIT_STORE(32, o1)
    SPLIT_STORE(64, o2)
    SPLIT_STORE(96, o3)
    #undef SPLIT_STORE
}

// ---------------------------------------------------------------------------
// GEMM2 via wmma bf16 split (3-pass), A fragments straight from global (L2).
// saved[N,64] = 0.25 * agg[N,256] @ Wcat[256,64] + bias; fused BN stats.
// smem: W hi/lo (64KB); epilogue reuses the sWh region for accumulator spill.
// No syncthreads in the mainloop.
// ---------------------------------------------------------------------------
#define G2R 128
__global__ __launch_bounds__(256) void gemm2w_kernel(const __nv_bfloat16* __restrict__ Ah,
                                                     const __nv_bfloat16* __restrict__ Al,
                                                     const __nv_bfloat16* __restrict__ Wh,
                                                     const __nv_bfloat16* __restrict__ Wl,
                                                     const float* __restrict__ bias,
                                                     float* __restrict__ out,
                                                     float* __restrict__ stats) {
    extern __shared__ char smraw[];
    __nv_bfloat16* sWh = (__nv_bfloat16*)smraw;        // 16384 bf16 (32KB)
    __nv_bfloat16* sWl = sWh + 16384;                  // 16384 bf16 (32KB)
    float* sOut = (float*)sWh;                         // reused after mainloop

    int t = threadIdx.x;
    int warp = t >> 5;                                 // 8 warps, 16 rows each

    for (int i = t; i < 2048; i += 256) {
        ((uint4*)sWh)[i] = ((const uint4*)Wh)[i];
        ((uint4*)sWl)[i] = ((const uint4*)Wl)[i];
    }
    __syncthreads();

    int row0 = blockIdx.x * G2R;
    const __nv_bfloat16* aph = Ah + (size_t)(row0 + warp * 16) * 256;
    const __nv_bfloat16* apl = Al + (size_t)(row0 + warp * 16) * 256;

    wmma::fragment<wmma::accumulator, 16, 16, 16, float> acc[4];
    #pragma unroll
    for (int nt = 0; nt < 4; nt++) wmma::fill_fragment(acc[nt], 0.f);

    #pragma unroll 4
    for (int ks = 0; ks < 16; ks++) {
        wmma::fragment<wmma::matrix_a, 16, 16, 16, __nv_bfloat16, wmma::row_major> ah, al;
        wmma::load_matrix_sync(ah, aph + ks * 16, 256);
        wmma::load_matrix_sync(al, apl + ks * 16, 256);
        #pragma unroll
        for (int nt = 0; nt < 4; nt++) {
            wmma::fragment<wmma::matrix_b, 16, 16, 16, __nv_bfloat16, wmma::row_major> bh, bl;
            wmma::load_matrix_sync(bh, sWh + (ks * 16) * 64 + nt * 16, 64);
            wmma::load_matrix_sync(bl, sWl + (ks * 16) * 64 + nt * 16, 64);
            wmma::mma_sync(acc[nt], ah, bh, acc[nt]);
            wmma::mma_sync(acc[nt], al, bh, acc[nt]);
            wmma::mma_sync(acc[nt], ah, bl, acc[nt]);
        }
    }
    __syncthreads();   // done reading sWh/sWl; safe to overwrite with sOut
    #pragma unroll
    for (int nt = 0; nt < 4; nt++)
        wmma::store_matrix_sync(sOut + (warp * 16) * 64 + nt * 16, acc[nt], 64,
                                wmma::mem_row_major);
    __syncthreads();

    // epilogue: 0.25*v + bias; write out; per-channel stats
    int c = t & 63, rg = t >> 6;
    float bb = bias[c];
    float s1 = 0.f, s2 = 0.f;
    for (int r = rg; r < G2R; r += 4) {
        int row = row0 + r;
        if (row < N_NODES) {
            float o = 0.25f * sOut[r * 64 + c] + bb;
            out[(size_t)row * 64 + c] = o;
            s1 += o; s2 += o * o;
        }
    }
    __shared__ float red[512];
    red[t] = s1; red[256 + t] = s2;
    __syncthreads();
    if (t < 64) {
        float a = red[t] + red[64 + t] + red[128 + t] + red[192 + t];
        float b = red[256 + t] + red[320 + t] + red[384 + t] + red[448 + t];
        atomicAdd(&stats[t], a);
        atomicAdd(&stats[64 + t], b);
    }
}

// ---------------------------------------------------------------------------
// BN normalize + relu (final layer output)
// ---------------------------------------------------------------------------
__global__ __launch_bounds__(256) void bn_norm_kernel(const float* __restrict__ xs,
                                                      const float* __restrict__ stats,
                                                      const float* __restrict__ gamma,
                                                      const float* __restrict__ beta,
                                                      float* __restrict__ out) {
    __shared__ float sc[64], sh[64];
    int t = threadIdx.x;
    if (t < 64) {
        const float invN = 1.f / (float)N_NODES;
        float mu = stats[t] * invN;
        float var = stats[64 + t] * invN - mu * mu;
        float rs = rsqrtf(var + 1e-5f);
        float g = gamma[t];
        sc[t] = g * rs;
        sh[t] = beta[t] - g * mu * rs;
    }
    __syncthreads();
    int i = blockIdx.x * blockDim.x + t;
    if (i >= NC) return;
    int c = i & 63;
    out[i] = fmaxf(fmaf(xs[i], sc[c], sh[c]), 0.f);
}

// ---------------------------------------------------------------------------
// Fused: BN normalize + relu (layer 1) AND layer-2 attention logits.
// ---------------------------------------------------------------------------
__global__ __launch_bounds__(256) void bn_norm_al_kernel(const float* __restrict__ xs,
                                                         const float* __restrict__ stats,
                                                         const float* __restrict__ gamma,
                                                         const float* __restrict__ beta,
                                                         const float* __restrict__ wa2,
                                                         float* __restrict__ h1,
                                                         float* __restrict__ als,
                                                         float* __restrict__ ald) {
    __shared__ float swa[512];
    __shared__ float sc[64], sh[64];
    int t = threadIdx.x;
    for (int i = t; i < 512; i += 256) swa[i] = wa2[i];
    if (t < 64) {
        const float invN = 1.f / (float)N_NODES;
        float mu = stats[t] * invN;
        float var = stats[64 + t] * invN - mu * mu;
        float rs = rsqrtf(var + 1e-5f);
        float g = gamma[t];
        sc[t] = g * rs;
        sh[t] = beta[t] - g * mu * rs;
    }
    __syncthreads();
    int w = (blockIdx.x * blockDim.x + t) >> 5;
    int lane = t & 31;
    if (w >= N_NODES) return;
    int c0 = 2 * lane, c1 = c0 + 1;
    float2 v = ((const float2*)xs)[(size_t)w * 32 + lane];
    float y0 = fmaxf(fmaf(v.x, sc[c0], sh[c0]), 0.f);
    float y1 = fmaxf(fmaf(v.y, sc[c1], sh[c1]), 0.f);
    ((float2*)h1)[(size_t)w * 32 + lane] = make_float2(y0, y1);
    float rs4[4], rd4[4];
    #pragma unroll
    for (int h = 0; h < 4; h++) {
        rs4[h] = y0 * swa[h * 64 + c0] + y1 * swa[h * 64 + c1];
        rd4[h] = y0 * swa[256 + h * 64 + c0] + y1 * swa[256 + h * 64 + c1];
    }
    #pragma unroll
    for (int o = 16; o; o >>= 1) {
        #pragma unroll
        for (int h = 0; h < 4; h++) {
            rs4[h] += __shfl_xor_sync(0xffffffffu, rs4[h], o);
            rd4[h] += __shfl_xor_sync(0xffffffffu, rd4[h], o);
        }
    }
    if (lane == 0) {
        *(float4*)(als + (size_t)w * 4) = make_float4(rs4[0], rs4[1], rs4[2], rs4[3]);
        *(float4*)(ald + (size_t)w * 4) = make_float4(rd4[0], rd4[1], rd4[2], rd4[3]);
    }
}

// ---------------------------------------------------------------------------
// host
// ---------------------------------------------------------------------------
extern "C" void kernel_launch(void* const* d_in, const int* in_sizes, int n_in,
                              void* d_out, int out_size) {
    const float* x   = (const float*)d_in[0];
    const void*  ei  = d_in[1];
    const int*   ei32 = (const int*)d_in[1];
    const float* W0  = (const float*)d_in[3];
    const float* as0 = (const float*)d_in[4];
    const float* ad0 = (const float*)d_in[5];
    const float* b0  = (const float*)d_in[6];
    const float* g0  = (const float*)d_in[7];
    const float* bt0 = (const float*)d_in[8];
    const float* W1  = (const float*)d_in[9];
    const float* as1 = (const float*)d_in[10];
    const float* ad1 = (const float*)d_in[11];
    const float* b1  = (const float*)d_in[12];
    const float* g1  = (const float*)d_in[13];
    const float* bt1 = (const float*)d_in[14];

    void* sp = nullptr;
    cudaGetSymbolAddress(&sp, g_scratch);
    float* S = (float*)sp;
    __nv_bfloat16* aggh = (__nv_bfloat16*)(S + OFF_AGG);
    __nv_bfloat16* aggl = aggh + (size_t)N_NODES * 256;
    float* als    = S + OFF_ALS;
    float* ald    = S + OFF_ALD;
    float* h1     = S + OFF_H1;
    float* stats  = S + OFF_STATS;   // [0:128) layer1, [128:256) layer2
    float* wa     = S + OFF_WA;      // [0:512) layer1, [512:1024) layer2
    __nv_bfloat16* whl = (__nv_bfloat16*)(S + OFF_WHL);
    int* deg  = (int*)(S + OFF_DEG);
    int* rowp = (int*)(S + OFF_ROWP);
    int* cur  = (int*)(S + OFF_CUR);
    int* csrc = (int*)(S + OFF_CSRC);

    const int G2_SMEM = 65536;   // W hi/lo only; sOut overlays sWh
    cudaFuncSetAttribute(gemm2w_kernel, cudaFuncAttributeMaxDynamicSharedMemorySize, G2_SMEM);

    float* out_final = (float*)d_out;
    float* out_saved = out_final + NC;

    const int NWARP_GRID = (N_NODES * 32 + 255) / 256;
    const int G2_GRID = (N_NODES + G2R - 1) / G2R;

    // ---- CSR build (once) ----
    init_kernel<<<(N_NODES + 255) / 256, 256>>>(ei32, deg);
    hist_kernel<<<(E_TOT / 2 + 255) / 256, 256>>>(ei, deg);
    scan_kernel<<<1, SCAN_T>>>(deg, rowp, cur);
    scatter_kernel<<<(E_TOT / 2 + 255) / 256, 256>>>(ei, cur, csrc);

    // ---- per-layer weight prep ----
    wa_kernel<<<2, 256>>>(W0, as0, ad0, W1, as1, ad1, wa, stats);
    {
        dim3 g(64, 2);
        wcat_kernel<<<g, 256>>>(W0, W1, whl);
    }

    // ---- layer 1 ----
    al_kernel<<<NWARP_GRID, 256>>>(x, wa, als, ald);
    dst_kernel<<<NWARP_GRID, 256>>>(rowp, deg, csrc, als, ald, x,
                                    (__nv_bfloat162*)aggh, (__nv_bfloat162*)aggl);
    gemm2w_kernel<<<G2_GRID, 256, G2_SMEM>>>(aggh, aggl, whl, whl + 16384, b0,
                                             out_saved, stats);
    bn_norm_al_kernel<<<NWARP_GRID, 256>>>(out_saved, stats, g0, bt0, wa + 512, h1, als, ald);

    // ---- layer 2 ----
    dst_kernel<<<NWARP_GRID, 256>>>(rowp, deg, csrc, als, ald, h1,
                                    (__nv_bfloat162*)aggh, (__nv_bfloat162*)aggl);
    gemm2w_kernel<<<G2_GRID, 256, G2_SMEM>>>(aggh, aggl, whl + 32768, whl + 49152, b1,
                                             out_saved, stats + 128);
    bn_norm_kernel<<<(NC + 255) / 256, 256>>>(out_saved, stats + 128, g1, bt1, out_final);
}

// round 14
// speedup vs baseline: 1.5721x; 1.5721x over previous
#include <cuda_runtime.h>
#include <math.h>

#define N_NODES 50000
#define N_EDGES 800000
#define E_TOT   850000          // + self loops
#define C       64
#define NC      (N_NODES * C)   // 3,200,000
#define NH      (N_NODES * 4)   // 200,000

// ---- scratch layout (floats; ints aliased) ----
#define OFF_AGG   0
#define SZ_AGG    (N_NODES * 256)          // 12,800,000
#define OFF_ALS   (OFF_AGG + SZ_AGG)
#define OFF_ALD   (OFF_ALS + NH)
#define OFF_H1    (OFF_ALD + NH)
#define OFF_STATS (OFF_H1 + NC)            // 256 (two layers x 128)
#define OFF_WA    (OFF_STATS + 256)        // 1024 (two layers x 512)
#define OFF_DEG   (OFF_WA + 1024)          // ints
#define OFF_ROWP  (OFF_DEG + N_NODES)
#define OFF_CUR   (OFF_ROWP + N_NODES)
#define OFF_CSRC  (OFF_CUR + N_NODES)
#define SCRATCH_TOTAL (OFF_CSRC + E_TOT)

__device__ __align__(16) float g_scratch[SCRATCH_TOTAL];
__device__ int g_is64;

__device__ __forceinline__ float lrelu(float x) { return x > 0.f ? x : 0.2f * x; }

__device__ __forceinline__ void edge_endpoints(const void* ei, int e, int& s, int& d) {
    if (e < N_EDGES) {
        if (g_is64) {
            const long long* p = (const long long*)ei;
            s = (int)p[e]; d = (int)p[N_EDGES + e];
        } else {
            const int* p = (const int*)ei;
            s = p[e]; d = p[N_EDGES + e];
        }
    } else {
        s = d = e - N_EDGES;
    }
}

// ---------------------------------------------------------------------------
// init: zero degree counters + detect edge dtype
// ---------------------------------------------------------------------------
__global__ void init_kernel(const int* __restrict__ ei32, int* __restrict__ deg) {
    int i = blockIdx.x * blockDim.x + threadIdx.x;
    if (i == 0) {
        int all0 = 1;
        #pragma unroll 8
        for (int k = 0; k < 64; k++) all0 &= (ei32[2 * k + 1] == 0);
        g_is64 = all0;
    }
    if (i < N_NODES) deg[i] = 0;
}

// ---------------------------------------------------------------------------
// hist: 4 edges per thread, vectorized dst loads (latency-bound -> more MLP)
// ---------------------------------------------------------------------------
__global__ void hist_kernel(const void* __restrict__ ei, int* __restrict__ deg) {
    int t = blockIdx.x * blockDim.x + threadIdx.x;
    int e0 = t * 4;
    if (e0 >= E_TOT) return;
    if (e0 + 3 < N_EDGES) {
        int d0, d1, d2, d3;
        if (g_is64) {
            const longlong2* p = (const longlong2*)((const long long*)ei + N_EDGES);
            longlong2 a = p[2 * t], b = p[2 * t + 1];
            d0 = (int)a.x; d1 = (int)a.y; d2 = (int)b.x; d3 = (int)b.y;
        } else {
            int4 dd = ((const int4*)((const int*)ei + N_EDGES))[t];
            d0 = dd.x; d1 = dd.y; d2 = dd.z; d3 = dd.w;
        }
        atomicAdd(&deg[d0], 1);
        atomicAdd(&deg[d1], 1);
        atomicAdd(&deg[d2], 1);
        atomicAdd(&deg[d3], 1);
    } else {
        for (int e = e0; e < e0 + 4 && e < E_TOT; e++) {
            int s, d; edge_endpoints(ei, e, s, d); (void)s;
            atomicAdd(&deg[d], 1);
        }
    }
}

#define SCAN_T 1024
#define SCAN_CHUNK 49
__global__ __launch_bounds__(SCAN_T) void scan_kernel(const int* __restrict__ deg,
                                                      int* __restrict__ row_ptr,
                                                      int* __restrict__ cursor) {
    __shared__ int sm[SCAN_T];
    int t = threadIdx.x;
    int base = t * SCAN_CHUNK;
    int s = 0;
    for (int i = 0; i < SCAN_CHUNK; i++) {
        int idx = base + i;
        if (idx < N_NODES) s += deg[idx];
    }
    sm[t] = s;
    __syncthreads();
    for (int off = 1; off < SCAN_T; off <<= 1) {
        int v = 0;
        if (t >= off) v = sm[t - off];
        __syncthreads();
        if (t >= off) sm[t] += v;
        __syncthreads();
    }
    int ex = (t == 0) ? 0 : sm[t - 1];
    for (int i = 0; i < SCAN_CHUNK; i++) {
        int idx = base + i;
        if (idx < N_NODES) {
            row_ptr[idx] = ex;
            cursor[idx] = ex;
            ex += deg[idx];
        }
    }
}

// ---------------------------------------------------------------------------
// scatter: 4 edges per thread, vectorized loads
// ---------------------------------------------------------------------------
__global__ void scatter_kernel(const void* __restrict__ ei, int* __restrict__ cursor,
                               int* __restrict__ csr_src) {
    int t = blockIdx.x * blockDim.x + threadIdx.x;
    int e0 = t * 4;
    if (e0 >= E_TOT) return;
    if (e0 + 3 < N_EDGES) {
        int s0, s1, s2, s3, d0, d1, d2, d3;
        if (g_is64) {
            const longlong2* ps = (const longlong2*)((const long long*)ei);
            const longlong2* pd = (const longlong2*)((const long long*)ei + N_EDGES);
            longlong2 sa = ps[2 * t], sb = ps[2 * t + 1];
            longlong2 da = pd[2 * t], db = pd[2 * t + 1];
            s0 = (int)sa.x; s1 = (int)sa.y; s2 = (int)sb.x; s3 = (int)sb.y;
            d0 = (int)da.x; d1 = (int)da.y; d2 = (int)db.x; d3 = (int)db.y;
        } else {
            int4 ss = ((const int4*)((const int*)ei))[t];
            int4 dd = ((const int4*)((const int*)ei + N_EDGES))[t];
            s0 = ss.x; s1 = ss.y; s2 = ss.z; s3 = ss.w;
            d0 = dd.x; d1 = dd.y; d2 = dd.z; d3 = dd.w;
        }
        int p0 = atomicAdd(&cursor[d0], 1);
        int p1 = atomicAdd(&cursor[d1], 1);
        int p2 = atomicAdd(&cursor[d2], 1);
        int p3 = atomicAdd(&cursor[d3], 1);
        csr_src[p0] = s0;
        csr_src[p1] = s1;
        csr_src[p2] = s2;
        csr_src[p3] = s3;
    } else {
        for (int e = e0; e < e0 + 4 && e < E_TOT; e++) {
            int s, d; edge_endpoints(ei, e, s, d);
            int pos = atomicAdd(&cursor[d], 1);
            csr_src[pos] = s;
        }
    }
}

// ---------------------------------------------------------------------------
// wa precompute for BOTH layers (block per layer) + zero stats
// ---------------------------------------------------------------------------
__global__ void wa_kernel(const float* __restrict__ W0, const float* __restrict__ as0,
                          const float* __restrict__ ad0,
                          const float* __restrict__ W1, const float* __restrict__ as1,
                          const float* __restrict__ ad1,
                          float* __restrict__ wa, float* __restrict__ stats) {
    int l = blockIdx.x;
    const float* W    = l ? W1 : W0;
    const float* asrc = l ? as1 : as0;
    const float* adst = l ? ad1 : ad0;
    int t = threadIdx.x;            // 256 threads
    int h = t >> 6, ci = t & 63;
    float s = 0.f, d = 0.f;
    #pragma unroll 8
    for (int c = 0; c < 64; c++) {
        float w = W[ci * 256 + h * 64 + c];
        s += w * asrc[h * 64 + c];
        d += w * adst[h * 64 + c];
    }
    wa[l * 512 + h * 64 + ci] = s;
    wa[l * 512 + 256 + h * 64 + ci] = d;
    if (t < 128) stats[l * 128 + t] = 0.f;
}

// ---------------------------------------------------------------------------
// attention logits, warp per node: lane owns channels (2l, 2l+1); coalesced
// ---------------------------------------------------------------------------
__global__ __launch_bounds__(256) void al_kernel(const float* __restrict__ x,
                                                 const float* __restrict__ wa,
                                                 float* __restrict__ als,
                                                 float* __restrict__ ald) {
    __shared__ float swa[512];
    for (int i = threadIdx.x; i < 512; i += 256) swa[i] = wa[i];
    __syncthreads();
    int w = (blockIdx.x * blockDim.x + threadIdx.x) >> 5;
    int lane = threadIdx.x & 31;
    if (w >= N_NODES) return;
    float2 v = ((const float2*)x)[(size_t)w * 32 + lane];
    float rs[4], rd[4];
    #pragma unroll
    for (int h = 0; h < 4; h++) {
        rs[h] = v.x * swa[h * 64 + 2 * lane] + v.y * swa[h * 64 + 2 * lane + 1];
        rd[h] = v.x * swa[256 + h * 64 + 2 * lane] + v.y * swa[256 + h * 64 + 2 * lane + 1];
    }
    #pragma unroll
    for (int o = 16; o; o >>= 1) {
        #pragma unroll
        for (int h = 0; h < 4; h++) {
            rs[h] += __shfl_xor_sync(0xffffffffu, rs[h], o);
            rd[h] += __shfl_xor_sync(0xffffffffu, rd[h], o);
        }
    }
    if (lane == 0) {
        *(float4*)(als + (size_t)w * 4) = make_float4(rs[0], rs[1], rs[2], rs[3]);
        *(float4*)(ald + (size_t)w * 4) = make_float4(rd[0], rd[1], rd[2], rd[3]);
    }
}

// ---------------------------------------------------------------------------
// SINGLE-PASS fused softmax + gather. Warp per dst node.
// ---------------------------------------------------------------------------
__global__ __launch_bounds__(256) void dst_kernel(const int* __restrict__ row_ptr,
                                                  const int* __restrict__ deg,
                                                  const int* __restrict__ csr_src,
                                                  const float* __restrict__ als,
                                                  const float* __restrict__ ald,
                                                  const float* __restrict__ x,
                                                  float* __restrict__ agg) {
    int w = (blockIdx.x * blockDim.x + threadIdx.x) >> 5;
    int lane = threadIdx.x & 31;
    if (w >= N_NODES) return;
    int start = row_ptr[w];
    int n = deg[w];
    float4 ad = *(const float4*)(ald + (size_t)w * 4);

    float4 dl = make_float4(0.f, 0.f, 0.f, 0.f);
    float2 r0 = make_float2(0.f, 0.f), r1 = r0, r2 = r0, r3 = r0;

    for (int base = 0; base < n; base += 32) {
        int j = base + lane;
        int s = 0;
        float4 p = make_float4(0.f, 0.f, 0.f, 0.f);
        if (j < n) {
            s = csr_src[start + j];
            float4 a = *(const float4*)(als + (size_t)s * 4);
            p.x = __expf(lrelu(a.x + ad.x));
            p.y = __expf(lrelu(a.y + ad.y));
            p.z = __expf(lrelu(a.z + ad.z));
            p.w = __expf(lrelu(a.w + ad.w));
        }
        dl.x += p.x; dl.y += p.y; dl.z += p.z; dl.w += p.w;
        int cnt = n - base; if (cnt > 32) cnt = 32;
        #pragma unroll 4
        for (int jj = 0; jj < cnt; jj++) {
            int ss   = __shfl_sync(0xffffffffu, s, jj);
            float a0 = __shfl_sync(0xffffffffu, p.x, jj);
            float a1 = __shfl_sync(0xffffffffu, p.y, jj);
            float a2 = __shfl_sync(0xffffffffu, p.z, jj);
            float a3 = __shfl_sync(0xffffffffu, p.w, jj);
            float2 v = *((const float2*)x + (size_t)ss * 32 + lane);
            r0.x += a0 * v.x; r0.y += a0 * v.y;
            r1.x += a1 * v.x; r1.y += a1 * v.y;
            r2.x += a2 * v.x; r2.y += a2 * v.y;
            r3.x += a3 * v.x; r3.y += a3 * v.y;
        }
    }
    #pragma unroll
    for (int o = 16; o; o >>= 1) {
        dl.x += __shfl_xor_sync(0xffffffffu, dl.x, o);
        dl.y += __shfl_xor_sync(0xffffffffu, dl.y, o);
        dl.z += __shfl_xor_sync(0xffffffffu, dl.z, o);
        dl.w += __shfl_xor_sync(0xffffffffu, dl.w, o);
    }
    float i0 = 1.0f / (dl.x + 1e-16f);
    float i1 = 1.0f / (dl.y + 1e-16f);
    float i2 = 1.0f / (dl.z + 1e-16f);
    float i3 = 1.0f / (dl.w + 1e-16f);
    float2* ag = (float2*)(agg + (size_t)w * 256);
    ag[lane]      = make_float2(r0.x * i0, r0.y * i0);
    ag[32 + lane] = make_float2(r1.x * i1, r1.y * i1);
    ag[64 + lane] = make_float2(r2.x * i2, r2.y * i2);
    ag[96 + lane] = make_float2(r3.x * i3, r3.y * i3);
}

// ---------------------------------------------------------------------------
// GEMM2 + fused BN stats: saved = 0.25*agg@Wcat + bias; stats += (sum, sumsq)
// ---------------------------------------------------------------------------
#define G2_ROWS 128
__global__ __launch_bounds__(256) void gemm2s_kernel(const float* __restrict__ agg,
                                                     const float* __restrict__ W,
                                                     const float* __restrict__ bias,
                                                     float* __restrict__ out,
                                                     float* __restrict__ stats) {
    extern __shared__ float sm[];
    float* sW = sm;              // 16384 floats
    float* sA = sm + 16384;      // 64*132 floats
    const float4* W4 = (const float4*)W;
    float4* sW4 = (float4*)sW;
    #pragma unroll 4
    for (int i = threadIdx.x; i < 4096; i += 256) sW4[i] = W4[i];

    int row0 = blockIdx.x * G2_ROWS;
    int cg = threadIdx.x & 15;    // 4 cols each -> 64 cols
    int rg = threadIdx.x >> 4;    // 8 rows each -> 128 rows
    float acc[8][4];
    #pragma unroll
    for (int r = 0; r < 8; r++) { acc[r][0] = acc[r][1] = acc[r][2] = acc[r][3] = 0.f; }

    for (int kc = 0; kc < 4; kc++) {
        __syncthreads();
        for (int i = threadIdx.x; i < 2048; i += 256) {
            int r = i >> 4, c4 = i & 15;
            float4 v = make_float4(0.f, 0.f, 0.f, 0.f);
            int row = row0 + r;
            if (row < N_NODES) v = *(const float4*)(agg + (size_t)row * 256 + kc * 64 + c4 * 4);
            sA[(c4 * 4 + 0) * 132 + r] = v.x;
            sA[(c4 * 4 + 1) * 132 + r] = v.y;
            sA[(c4 * 4 + 2) * 132 + r] = v.z;
            sA[(c4 * 4 + 3) * 132 + r] = v.w;
        }
        __syncthreads();
        const float* wbase = sW + kc * 64;
        #pragma unroll 4
        for (int k = 0; k < 64; k++) {
            float4 b4 = *(const float4*)(wbase + k * 256 + cg * 4);
            const float* arow = sA + k * 132 + rg * 8;
            float4 a0 = *(const float4*)(arow);
            float4 a1 = *(const float4*)(arow + 4);
            float av[8] = {a0.x, a0.y, a0.z, a0.w, a1.x, a1.y, a1.z, a1.w};
            #pragma unroll
            for (int r = 0; r < 8; r++) {
                acc[r][0] += av[r] * b4.x;
                acc[r][1] += av[r] * b4.y;
                acc[r][2] += av[r] * b4.z;
                acc[r][3] += av[r] * b4.w;
            }
        }
    }
    float4 bb = *((const float4*)bias + cg);
    float s1[4] = {0.f, 0.f, 0.f, 0.f}, s2[4] = {0.f, 0.f, 0.f, 0.f};
    #pragma unroll
    for (int r = 0; r < 8; r++) {
        int row = row0 + rg * 8 + r;
        if (row < N_NODES) {
            float o0 = 0.25f * acc[r][0] + bb.x;
            float o1 = 0.25f * acc[r][1] + bb.y;
            float o2 = 0.25f * acc[r][2] + bb.z;
            float o3 = 0.25f * acc[r][3] + bb.w;
            *(float4*)(out + (size_t)row * 64 + cg * 4) = make_float4(o0, o1, o2, o3);
            s1[0] += o0; s1[1] += o1; s1[2] += o2; s1[3] += o3;
            s2[0] += o0 * o0; s2[1] += o1 * o1; s2[2] += o2 * o2; s2[3] += o3 * o3;
        }
    }
    __syncthreads();
    #pragma unroll
    for (int k = 0; k < 4; k++) {
        sA[rg * 64 + cg * 4 + k] = s1[k];
        sA[1024 + rg * 64 + cg * 4 + k] = s2[k];
    }
    __syncthreads();
    int t = threadIdx.x;
    if (t < 64) {
        float a = 0.f, b = 0.f;
        #pragma unroll
        for (int g = 0; g < 16; g++) {
            a += sA[g * 64 + t];
            b += sA[1024 + g * 64 + t];
        }
        atomicAdd(&stats[t], a);
        atomicAdd(&stats[64 + t], b);
    }
}

// ---------------------------------------------------------------------------
// BN normalize + relu (final layer output)
// ---------------------------------------------------------------------------
__global__ __launch_bounds__(256) void bn_norm_kernel(const float* __restrict__ xs,
                                                      const float* __restrict__ stats,
                                                      const float* __restrict__ gamma,
                                                      const float* __restrict__ beta,
                                                      float* __restrict__ out) {
    __shared__ float sc[64], sh[64];
    int t = threadIdx.x;
    if (t < 64) {
        const float invN = 1.f / (float)N_NODES;
        float mu = stats[t] * invN;
        float var = stats[64 + t] * invN - mu * mu;
        float rs = rsqrtf(var + 1e-5f);
        float g = gamma[t];
        sc[t] = g * rs;
        sh[t] = beta[t] - g * mu * rs;
    }
    __syncthreads();
    int i = blockIdx.x * blockDim.x + t;
    if (i >= NC) return;
    int c = i & 63;
    out[i] = fmaxf(fmaf(xs[i], sc[c], sh[c]), 0.f);
}

// ---------------------------------------------------------------------------
// Fused: BN normalize + relu (layer 1) AND layer-2 attention logits.
// ---------------------------------------------------------------------------
__global__ __launch_bounds__(256) void bn_norm_al_kernel(const float* __restrict__ xs,
                                                         const float* __restrict__ stats,
                                                         const float* __restrict__ gamma,
                                                         const float* __restrict__ beta,
                                                         const float* __restrict__ wa2,
                                                         float* __restrict__ h1,
                                                         float* __restrict__ als,
                                                         float* __restrict__ ald) {
    __shared__ float swa[512];
    __shared__ float sc[64], sh[64];
    int t = threadIdx.x;
    for (int i = t; i < 512; i += 256) swa[i] = wa2[i];
    if (t < 64) {
        const float invN = 1.f / (float)N_NODES;
        float mu = stats[t] * invN;
        float var = stats[64 + t] * invN - mu * mu;
        float rs = rsqrtf(var + 1e-5f);
        float g = gamma[t];
        sc[t] = g * rs;
        sh[t] = beta[t] - g * mu * rs;
    }
    __syncthreads();
    int w = (blockIdx.x * blockDim.x + t) >> 5;
    int lane = t & 31;
    if (w >= N_NODES) return;
    int c0 = 2 * lane, c1 = c0 + 1;
    float2 v = ((const float2*)xs)[(size_t)w * 32 + lane];
    float y0 = fmaxf(fmaf(v.x, sc[c0], sh[c0]), 0.f);
    float y1 = fmaxf(fmaf(v.y, sc[c1], sh[c1]), 0.f);
    ((float2*)h1)[(size_t)w * 32 + lane] = make_float2(y0, y1);
    float rs4[4], rd4[4];
    #pragma unroll
    for (int h = 0; h < 4; h++) {
        rs4[h] = y0 * swa[h * 64 + c0] + y1 * swa[h * 64 + c1];
        rd4[h] = y0 * swa[256 + h * 64 + c0] + y1 * swa[256 + h * 64 + c1];
    }
    #pragma unroll
    for (int o = 16; o; o >>= 1) {
        #pragma unroll
        for (int h = 0; h < 4; h++) {
            rs4[h] += __shfl_xor_sync(0xffffffffu, rs4[h], o);
            rd4[h] += __shfl_xor_sync(0xffffffffu, rd4[h], o);
        }
    }
    if (lane == 0) {
        *(float4*)(als + (size_t)w * 4) = make_float4(rs4[0], rs4[1], rs4[2], rs4[3]);
        *(float4*)(ald + (size_t)w * 4) = make_float4(rd4[0], rd4[1], rd4[2], rd4[3]);
    }
}

// ---------------------------------------------------------------------------
// host
// ---------------------------------------------------------------------------
extern "C" void kernel_launch(void* const* d_in, const int* in_sizes, int n_in,
                              void* d_out, int out_size) {
    const float* x   = (const float*)d_in[0];
    const void*  ei  = d_in[1];
    const int*   ei32 = (const int*)d_in[1];
    const float* W0  = (const float*)d_in[3];
    const float* as0 = (const float*)d_in[4];
    const float* ad0 = (const float*)d_in[5];
    const float* b0  = (const float*)d_in[6];
    const float* g0  = (const float*)d_in[7];
    const float* bt0 = (const float*)d_in[8];
    const float* W1  = (const float*)d_in[9];
    const float* as1 = (const float*)d_in[10];
    const float* ad1 = (const float*)d_in[11];
    const float* b1  = (const float*)d_in[12];
    const float* g1  = (const float*)d_in[13];
    const float* bt1 = (const float*)d_in[14];

    void* sp = nullptr;
    cudaGetSymbolAddress(&sp, g_scratch);
    float* S = (float*)sp;
    float* agg    = S + OFF_AGG;
    float* als    = S + OFF_ALS;
    float* ald    = S + OFF_ALD;
    float* h1     = S + OFF_H1;
    float* stats  = S + OFF_STATS;   // [0:128) layer1, [128:256) layer2
    float* wa     = S + OFF_WA;      // [0:512) layer1, [512:1024) layer2
    int* deg  = (int*)(S + OFF_DEG);
    int* rowp = (int*)(S + OFF_ROWP);
    int* cur  = (int*)(S + OFF_CUR);
    int* csrc = (int*)(S + OFF_CSRC);

    cudaFuncSetAttribute(gemm2s_kernel, cudaFuncAttributeMaxDynamicSharedMemorySize, 99328);

    float* out_final = (float*)d_out;
    float* out_saved = out_final + NC;

    const int NWARP_GRID = (N_NODES * 32 + 255) / 256;

    // ---- CSR build (once) ----
    init_kernel<<<(N_NODES + 255) / 256, 256>>>(ei32, deg);
    hist_kernel<<<(E_TOT / 4 + 255) / 256, 256>>>(ei, deg);
    scan_kernel<<<1, SCAN_T>>>(deg, rowp, cur);
    scatter_kernel<<<(E_TOT / 4 + 255) / 256, 256>>>(ei, cur, csrc);

    // ---- both layers' wa + zero stats ----
    wa_kernel<<<2, 256>>>(W0, as0, ad0, W1, as1, ad1, wa, stats);

    // ---- layer 1 ----
    al_kernel<<<NWARP_GRID, 256>>>(x, wa, als, ald);
    dst_kernel<<<NWARP_GRID, 256>>>(rowp, deg, csrc, als, ald, x, agg);
    gemm2s_kernel<<<(N_NODES + G2_ROWS - 1) / G2_ROWS, 256, 99328>>>(agg, W0, b0, out_saved, stats);
    bn_norm_al_kernel<<<NWARP_GRID, 256>>>(out_saved, stats, g0, bt0, wa + 512, h1, als, ald);

    // ---- layer 2 ----
    dst_kernel<<<NWARP_GRID, 256>>>(rowp, deg, csrc, als, ald, h1, agg);
    gemm2s_kernel<<<(N_NODES + G2_ROWS - 1) / G2_ROWS, 256, 99328>>>(agg, W1, b1, out_saved, stats + 128);
    bn_norm_kernel<<<(NC + 255) / 256, 256>>>(out_saved, stats + 128, g1, bt1, out_final);
}